// round 6
// baseline (speedup 1.0000x reference)
#include <cuda_runtime.h>
#include <math.h>

// Top2Router: x[16384,2048] fp32, W[8,2048], b[8]
// out (fp32 concat): top2_val[N*2] | top2_idx[N*2] | gate[N*8]
//
// Barrier-free streaming design:
//  - grid=#SMs, 1024 threads, balanced contiguous token ranges (mult of 8).
//  - warp owns 4 consecutive tokens; lane l covers k in {2l,2l+1} per
//    64-wide k-step (32 steps). x read DIRECT from gmem, coalesced LDG.64,
//    1-step lookahead. No smem x staging, no cp.async, no barriers in loop.
//  - W staged once in smem as wz[(p*2+j)*1024 + (k>>1)] (u64 expert-pair):
//    per-lane contiguous -> conflict-free LDS.64, 8 per warp-step.
//  - f32x2 accumulation (4 tok x 4 pairs), butterfly shuffle reduction,
//    in-register softmax + stable top2, direct stores.

#define D_MODEL  2048
#define NEXP     8
#define THREADS  1024
#define TOKW     4
#define NSTEP    (D_MODEL / 64)    // 32

typedef unsigned long long u64;

__device__ __forceinline__ u64 splat2(float v) {
    u64 r; asm("mov.b64 %0, {%1, %1};" : "=l"(r) : "f"(v)); return r;
}
__device__ __forceinline__ void ffma2(u64& a, u64 x, u64 w) {
    asm("fma.rn.f32x2 %0, %1, %2, %0;" : "+l"(a) : "l"(x), "l"(w));
}
__device__ __forceinline__ void add2(u64& a, u64 o) {
    asm("add.rn.f32x2 %0, %0, %1;" : "+l"(a) : "l"(o));
}

__global__ __launch_bounds__(THREADS, 1)
void top2_router_kernel(const float* __restrict__ x,
                        const float* __restrict__ W,
                        const float* __restrict__ b,
                        float* __restrict__ out,
                        int n_tok)
{
    extern __shared__ u64 wz[];                  // 8*1024 u64 = 64 KB

    const int tid  = threadIdx.x;
    const int w    = tid >> 5;
    const int lane = tid & 31;

    // ---- stage W: wz[(p*2+j)*1024 + kk] = (W[2p][2kk+j], W[2p+1][2kk+j])
    #pragma unroll
    for (int i = 0; i < 8; ++i) {
        int q   = tid + i * THREADS;             // 0..8191
        int p2j = q >> 10;
        int kk  = q & 1023;
        int k   = 2 * kk + (p2j & 1);
        int e0  = (p2j >> 1) * 2;
        float lo = W[e0 * D_MODEL + k];
        float hi = W[(e0 + 1) * D_MODEL + k];
        u64 v; asm("mov.b64 %0, {%1, %2};" : "=l"(v) : "f"(lo), "f"(hi));
        wz[q] = v;
    }
    __syncthreads();                             // only barrier in the kernel

    // balanced token range (units of 8 tokens)
    const int G     = gridDim.x;
    const int units = n_tok >> 3;
    const int s8    = (int)(((long long)blockIdx.x       * units) / G);
    const int e8    = (int)(((long long)(blockIdx.x + 1) * units) / G);
    const int tokenBase = s8 * 8;
    const int ntok_b    = (e8 - s8) * 8;         // <= 112 for G >= 152

    const int wtok = w * TOKW;                   // warp's token offset in block
    if (wtok >= ntok_b) return;                  // ntok_b % 8 == 0 -> clean cut

    const float* gxw = x + (size_t)(tokenBase + wtok) * D_MODEL + 2 * lane;

    u64 acc[TOKW][4];
    #pragma unroll
    for (int t = 0; t < TOKW; ++t)
        #pragma unroll
        for (int p = 0; p < 4; ++p) acc[t][p] = 0ull;

    u64 xc[TOKW], xn[TOKW];
    #pragma unroll
    for (int t = 0; t < TOKW; ++t)
        xc[t] = *reinterpret_cast<const u64*>(gxw + (size_t)t * D_MODEL);

    #pragma unroll 1
    for (int s = 0; s < NSTEP - 1; ++s) {
        const float* gnx = gxw + (s + 1) * 64;
        #pragma unroll
        for (int t = 0; t < TOKW; ++t)
            xn[t] = *reinterpret_cast<const u64*>(gnx + (size_t)t * D_MODEL);

        const int kk = s * 32 + lane;
        #pragma unroll
        for (int j = 0; j < 2; ++j) {
            u64 wp0 = wz[(0 * 2 + j) * 1024 + kk];
            u64 wp1 = wz[(1 * 2 + j) * 1024 + kk];
            u64 wp2 = wz[(2 * 2 + j) * 1024 + kk];
            u64 wp3 = wz[(3 * 2 + j) * 1024 + kk];
            #pragma unroll
            for (int t = 0; t < TOKW; ++t) {
                float lo, hi;
                asm("mov.b64 {%0, %1}, %2;" : "=f"(lo), "=f"(hi) : "l"(xc[t]));
                u64 xx = splat2(j ? hi : lo);
                ffma2(acc[t][0], xx, wp0);
                ffma2(acc[t][1], xx, wp1);
                ffma2(acc[t][2], xx, wp2);
                ffma2(acc[t][3], xx, wp3);
            }
        }
        #pragma unroll
        for (int t = 0; t < TOKW; ++t) xc[t] = xn[t];
    }
    // peeled last step
    {
        const int kk = (NSTEP - 1) * 32 + lane;
        #pragma unroll
        for (int j = 0; j < 2; ++j) {
            u64 wp0 = wz[(0 * 2 + j) * 1024 + kk];
            u64 wp1 = wz[(1 * 2 + j) * 1024 + kk];
            u64 wp2 = wz[(2 * 2 + j) * 1024 + kk];
            u64 wp3 = wz[(3 * 2 + j) * 1024 + kk];
            #pragma unroll
            for (int t = 0; t < TOKW; ++t) {
                float lo, hi;
                asm("mov.b64 {%0, %1}, %2;" : "=f"(lo), "=f"(hi) : "l"(xc[t]));
                u64 xx = splat2(j ? hi : lo);
                ffma2(acc[t][0], xx, wp0);
                ffma2(acc[t][1], xx, wp1);
                ffma2(acc[t][2], xx, wp2);
                ffma2(acc[t][3], xx, wp3);
            }
        }
    }

    // ---- butterfly reduction across 32 lanes (all lanes end with full sums)
    #pragma unroll
    for (int off = 16; off > 0; off >>= 1) {
        #pragma unroll
        for (int t = 0; t < TOKW; ++t)
            #pragma unroll
            for (int p = 0; p < 4; ++p) {
                u64 o = __shfl_xor_sync(0xffffffffu, acc[t][p], off);
                add2(acc[t][p], o);
            }
    }

    // ---- lanes 0..3: per-token softmax + stable top2, direct stores
    if (lane < TOKW) {
        const int g = tokenBase + wtok + lane;
        float gv[NEXP];
        #pragma unroll
        for (int p = 0; p < 4; ++p) {
            float lo, hi;
            asm("mov.b64 {%0, %1}, %2;" : "=f"(lo), "=f"(hi) : "l"(acc[lane][p]));
            gv[2 * p]     = lo + b[2 * p];
            gv[2 * p + 1] = hi + b[2 * p + 1];
        }
        float mx = -INFINITY;
        #pragma unroll
        for (int e = 0; e < NEXP; ++e) mx = fmaxf(mx, gv[e]);
        float ssum = 0.f;
        #pragma unroll
        for (int e = 0; e < NEXP; ++e) {
            gv[e] = __expf(gv[e] - mx);
            ssum += gv[e];
        }
        float inv = 1.f / ssum;
        #pragma unroll
        for (int e = 0; e < NEXP; ++e) gv[e] *= inv;

        float* gate_out = out + (size_t)n_tok * 4;
        float4 g0 = make_float4(gv[0], gv[1], gv[2], gv[3]);
        float4 g1 = make_float4(gv[4], gv[5], gv[6], gv[7]);
        *reinterpret_cast<float4*>(gate_out + (size_t)g * NEXP)     = g0;
        *reinterpret_cast<float4*>(gate_out + (size_t)g * NEXP + 4) = g1;

        int i1 = 0; float v1 = gv[0];
        #pragma unroll
        for (int e = 1; e < NEXP; ++e)
            if (gv[e] > v1) { v1 = gv[e]; i1 = e; }
        int i2 = -1; float v2 = -INFINITY;
        #pragma unroll
        for (int e = 0; e < NEXP; ++e)
            if (e != i1 && gv[e] > v2) { v2 = gv[e]; i2 = e; }

        *reinterpret_cast<float2*>(out + (size_t)g * 2) = make_float2(v1, v2);
        float* idx_out = out + (size_t)n_tok * 2;
        *reinterpret_cast<float2*>(idx_out + (size_t)g * 2) =
            make_float2((float)i1, (float)i2);
    }
}

extern "C" void kernel_launch(void* const* d_in, const int* in_sizes, int n_in,
                              void* d_out, int out_size)
{
    const float* x = (const float*)d_in[0];
    const float* W = (const float*)d_in[1];
    const float* b = (const float*)d_in[2];
    float* out = (float*)d_out;

    const int n_tok = in_sizes[0] / D_MODEL;     // 16384
    const int smem_bytes = 8 * 1024 * (int)sizeof(u64);   // 64 KB

    static int nsm = 0;
    if (nsm == 0) {
        cudaDeviceProp prop;
        cudaGetDeviceProperties(&prop, 0);
        nsm = prop.multiProcessorCount;          // 152 on GB300
        cudaFuncSetAttribute(top2_router_kernel,
                             cudaFuncAttributeMaxDynamicSharedMemorySize, smem_bytes);
    }

    top2_router_kernel<<<nsm, THREADS, smem_bytes>>>(x, W, b, out, n_tok);
}

// round 7
// speedup vs baseline: 1.1041x; 1.1041x over previous
#include <cuda_runtime.h>
#include <cuda.h>
#include <math.h>

// Top2Router: x[16384,2048] fp32, W[8,2048], b[8]
// out (fp32 concat): top2_val[N*2] | top2_idx[N*2] | gate[N*8]
//
// TMA experiment: R4 skeleton (512 thr, grid=#SMs, balanced ranges,
// warp=k-slice, f32x2 FMA, smem W broadcast) with x loaded via 2-D TMA
// (box 32 floats x ntok rows, SW128) into a 5-stage mbarrier ring,
// prefetch distance 3, one bar.sync per chunk.

#define D_MODEL  2048
#define NEXP     8
#define KCHUNK   64
#define NCHUNK   (D_MODEL / KCHUNK)   // 32
#define NSTAGE   5
#define THREADS  512
#define NWARP    16

typedef unsigned long long u64;

__device__ __forceinline__ void mbar_init(unsigned mb, unsigned count) {
    asm volatile("mbarrier.init.shared.b64 [%0], %1;" :: "r"(mb), "r"(count) : "memory");
}
__device__ __forceinline__ void mbar_expect_tx(unsigned mb, unsigned bytes) {
    asm volatile("mbarrier.arrive.expect_tx.shared.b64 _, [%0], %1;"
                 :: "r"(mb), "r"(bytes) : "memory");
}
__device__ __forceinline__ void mbar_wait(unsigned mb, unsigned parity) {
    asm volatile(
        "{\n\t.reg .pred P;\n"
        "W_%=:\n\t"
        "mbarrier.try_wait.parity.acquire.cta.shared::cta.b64 P, [%0], %1, 0x989680;\n\t"
        "@P bra D_%=;\n\t"
        "bra W_%=;\n"
        "D_%=:\n\t}"
        :: "r"(mb), "r"(parity) : "memory");
}
__device__ __forceinline__ void tma2d(unsigned dst, const CUtensorMap* map,
                                      int c0, int c1, unsigned mb) {
    asm volatile(
        "cp.async.bulk.tensor.2d.shared::cta.global.tile.mbarrier::complete_tx::bytes "
        "[%0], [%1, {%2, %3}], [%4];"
        :: "r"(dst), "l"(map), "r"(c0), "r"(c1), "r"(mb) : "memory");
}

__global__ __launch_bounds__(THREADS, 1)
void top2_router_kernel(const __grid_constant__ CUtensorMap mapHi,
                        const __grid_constant__ CUtensorMap mapLo,
                        const float* __restrict__ W,
                        const float* __restrict__ b,
                        float* __restrict__ out,
                        int n_tok, int hi)
{
    extern __shared__ float smem[];
    // layout: ring (5 * 64*hi floats, 1KB-aligned at offset 0) | wt (16384 f) | mbars
    const int stageFloats = 64 * hi;            // 2 tiles * 32 * hi
    const int ringFloats  = NSTAGE * stageFloats;
    float* ring = smem;
    float* wt   = smem + ringFloats;

    const unsigned smem_u32 = (unsigned)__cvta_generic_to_shared(smem);
    const unsigned ring_u32 = smem_u32;
    const unsigned mbar0    = smem_u32 + (unsigned)(ringFloats + 16384) * 4u;
    const unsigned stageBytes = (unsigned)stageFloats * 4u;
    const unsigned tileBytes  = (unsigned)(32 * hi) * 4u;

    const int tid  = threadIdx.x;
    const int w    = tid >> 5;
    const int lane = tid & 31;

    // balanced token range (units of 8 tokens)
    const int G     = gridDim.x;
    const int units = n_tok >> 3;
    const int s8    = (int)(((long long)blockIdx.x       * units) / G);
    const int e8    = (int)(((long long)(blockIdx.x + 1) * units) / G);
    const int tokenBase = s8 * 8;
    const int ntok_b    = (e8 - s8) * 8;        // hi or hi-8

    const CUtensorMap* mp = (ntok_b == hi) ? &mapHi : &mapLo;
    const unsigned chunkBytes = (unsigned)ntok_b * 256u;  // 2 tiles * ntok_b * 128B

    // ---- stage W transposed: wt[k*8+e] = W[e*2048+k]
    #pragma unroll
    for (int i = 0; i < (D_MODEL * NEXP) / THREADS; ++i) {   // 32
        int idx = tid + i * THREADS;
        int e = idx >> 11;
        int k = idx & (D_MODEL - 1);
        wt[k * NEXP + e] = W[idx];
    }
    if (tid == 0) {
        #pragma unroll
        for (int s = 0; s < NSTAGE; ++s) mbar_init(mbar0 + s * 8, 1);
    }
    __syncthreads();

    const u64* wt64 = reinterpret_cast<const u64*>(wt);

    u64 acc[4][4];
    #pragma unroll
    for (int t = 0; t < 4; ++t)
        #pragma unroll
        for (int p = 0; p < 4; ++p) acc[t][p] = 0ull;

    // prologue: issue chunks 0..2
    if (tid == 0) {
        #pragma unroll
        for (int c = 0; c < 3; ++c) {
            unsigned mb  = mbar0 + (c % NSTAGE) * 8;
            unsigned dst = ring_u32 + (unsigned)(c % NSTAGE) * stageBytes;
            mbar_expect_tx(mb, chunkBytes);
            tma2d(dst,             mp, c * KCHUNK,      tokenBase, mb);
            tma2d(dst + tileBytes, mp, c * KCHUNK + 32, tokenBase, mb);
        }
    }

    const int ws7   = w & 7;
    const int tsel  = (w >> 3);                 // tile 0/1 (k<32 / k>=32)
    const int tokLim = ntok_b - 1;

    for (int c = 0; c < NCHUNK; ++c) {
        if (tid == 0 && c + 3 < NCHUNK) {
            int cc = c + 3;
            unsigned mb  = mbar0 + (cc % NSTAGE) * 8;
            unsigned dst = ring_u32 + (unsigned)(cc % NSTAGE) * stageBytes;
            mbar_expect_tx(mb, chunkBytes);
            tma2d(dst,             mp, cc * KCHUNK,      tokenBase, mb);
            tma2d(dst + tileBytes, mp, cc * KCHUNK + 32, tokenBase, mb);
        }
        mbar_wait(mbar0 + (c % NSTAGE) * 8, (unsigned)((c / NSTAGE) & 1));
        __syncthreads();

        const float* tile = ring + (c % NSTAGE) * stageFloats + tsel * (32 * hi);

        // thread reads float4 of k [w*4, w*4+4) for 4 token groups (SW128)
        float4 xv[4];
        #pragma unroll
        for (int t = 0; t < 4; ++t) {
            int tok = lane + t * 32;
            int tokc = tok > tokLim ? tokLim : tok;
            xv[t] = reinterpret_cast<const float4*>(tile + tokc * 32)
                        [ws7 ^ (tokc & 7)];
        }

        #pragma unroll
        for (int j = 0; j < 4; ++j) {
            int kg = c * KCHUNK + w * 4 + j;
            u64 wp0 = wt64[kg * 4 + 0];
            u64 wp1 = wt64[kg * 4 + 1];
            u64 wp2 = wt64[kg * 4 + 2];
            u64 wp3 = wt64[kg * 4 + 3];
            #pragma unroll
            for (int t = 0; t < 4; ++t) {
                float xk = (j == 0) ? xv[t].x : (j == 1) ? xv[t].y
                         : (j == 2) ? xv[t].z : xv[t].w;
                u64 xx;
                asm("mov.b64 %0, {%1, %1};" : "=l"(xx) : "f"(xk));
                asm("fma.rn.f32x2 %0, %1, %2, %0;" : "+l"(acc[t][0]) : "l"(xx), "l"(wp0));
                asm("fma.rn.f32x2 %0, %1, %2, %0;" : "+l"(acc[t][1]) : "l"(xx), "l"(wp1));
                asm("fma.rn.f32x2 %0, %1, %2, %0;" : "+l"(acc[t][2]) : "l"(xx), "l"(wp2));
                asm("fma.rn.f32x2 %0, %1, %2, %0;" : "+l"(acc[t][3]) : "l"(xx), "l"(wp3));
            }
        }
    }
    __syncthreads();

    // ---- cross-warp reduction (reuse ring: 16*128*4 float2 = 16384 floats)
    float2* red = reinterpret_cast<float2*>(ring);
    #pragma unroll
    for (int t = 0; t < 4; ++t) {
        int tok = lane + t * 32;
        #pragma unroll
        for (int p = 0; p < 4; ++p) {
            float lo, hv;
            asm("mov.b64 {%0, %1}, %2;" : "=f"(lo), "=f"(hv) : "l"(acc[t][p]));
            red[(w * 128 + tok) * 4 + p] = make_float2(lo, hv);
        }
    }
    __syncthreads();

    float* lgs = ring + 16384;                   // 128*8 floats
    {
        int tok = tid >> 2;                      // 0..127
        int p   = tid & 3;
        float2 s = make_float2(0.f, 0.f);
        #pragma unroll
        for (int ww = 0; ww < NWARP; ++ww) {
            float2 v = red[(ww * 128 + tok) * 4 + p];
            s.x += v.x; s.y += v.y;
        }
        s.x += b[2 * p];
        s.y += b[2 * p + 1];
        reinterpret_cast<float2*>(lgs)[tok * 4 + p] = s;
    }
    __syncthreads();

    // ---- per-token softmax + stable top2
    if (tid < ntok_b) {
        const int g = tokenBase + tid;
        float gv[NEXP];
        float mx = -INFINITY;
        #pragma unroll
        for (int e = 0; e < NEXP; ++e) {
            gv[e] = lgs[tid * NEXP + e];
            mx = fmaxf(mx, gv[e]);
        }
        float ssum = 0.f;
        #pragma unroll
        for (int e = 0; e < NEXP; ++e) {
            gv[e] = __expf(gv[e] - mx);
            ssum += gv[e];
        }
        float inv = 1.f / ssum;
        #pragma unroll
        for (int e = 0; e < NEXP; ++e) gv[e] *= inv;

        float* gate_out = out + (size_t)n_tok * 4;
        float4 g0 = make_float4(gv[0], gv[1], gv[2], gv[3]);
        float4 g1 = make_float4(gv[4], gv[5], gv[6], gv[7]);
        *reinterpret_cast<float4*>(gate_out + (size_t)g * NEXP)     = g0;
        *reinterpret_cast<float4*>(gate_out + (size_t)g * NEXP + 4) = g1;

        int i1 = 0; float v1 = gv[0];
        #pragma unroll
        for (int e = 1; e < NEXP; ++e)
            if (gv[e] > v1) { v1 = gv[e]; i1 = e; }
        int i2 = -1; float v2 = -INFINITY;
        #pragma unroll
        for (int e = 0; e < NEXP; ++e)
            if (e != i1 && gv[e] > v2) { v2 = gv[e]; i2 = e; }

        *reinterpret_cast<float2*>(out + (size_t)g * 2) = make_float2(v1, v2);
        float* idx_out = out + (size_t)n_tok * 2;
        *reinterpret_cast<float2*>(idx_out + (size_t)g * 2) =
            make_float2((float)i1, (float)i2);
    }
}

// ---------------------------------------------------------------------------

typedef CUresult (*EncodeTiledFn)(
    CUtensorMap*, CUtensorMapDataType, cuuint32_t, void*,
    const cuuint64_t*, const cuuint64_t*, const cuuint32_t*, const cuuint32_t*,
    CUtensorMapInterleave, CUtensorMapSwizzle, CUtensorMapL2promotion,
    CUtensorMapFloatOOBfill);

static CUtensorMap g_mapHi, g_mapLo;
static const void* g_last_x = nullptr;
static int g_nsm = 0, g_hi = 0, g_smem = 0;

static void build_maps(const float* x, int n_tok, int hi, int lo)
{
    EncodeTiledFn enc = nullptr;
    cudaDriverEntryPointQueryResult qr;
    cudaGetDriverEntryPoint("cuTensorMapEncodeTiled", (void**)&enc,
                            cudaEnableDefault, &qr);
    cuuint64_t dims[2]    = {(cuuint64_t)D_MODEL, (cuuint64_t)n_tok};
    cuuint64_t strides[1] = {(cuuint64_t)D_MODEL * 4};
    cuuint32_t elem[2]    = {1, 1};
    cuuint32_t boxH[2]    = {32, (cuuint32_t)hi};
    cuuint32_t boxL[2]    = {32, (cuuint32_t)lo};
    enc(&g_mapHi, CU_TENSOR_MAP_DATA_TYPE_FLOAT32, 2, (void*)x,
        dims, strides, boxH, elem,
        CU_TENSOR_MAP_INTERLEAVE_NONE, CU_TENSOR_MAP_SWIZZLE_128B,
        CU_TENSOR_MAP_L2_PROMOTION_L2_128B, CU_TENSOR_MAP_FLOAT_OOB_FILL_NONE);
    enc(&g_mapLo, CU_TENSOR_MAP_DATA_TYPE_FLOAT32, 2, (void*)x,
        dims, strides, boxL, elem,
        CU_TENSOR_MAP_INTERLEAVE_NONE, CU_TENSOR_MAP_SWIZZLE_128B,
        CU_TENSOR_MAP_L2_PROMOTION_L2_128B, CU_TENSOR_MAP_FLOAT_OOB_FILL_NONE);
}

extern "C" void kernel_launch(void* const* d_in, const int* in_sizes, int n_in,
                              void* d_out, int out_size)
{
    const float* x = (const float*)d_in[0];
    const float* W = (const float*)d_in[1];
    const float* b = (const float*)d_in[2];
    float* out = (float*)d_out;

    const int n_tok = in_sizes[0] / D_MODEL;     // 16384

    if (g_nsm == 0) {
        cudaDeviceProp prop;
        cudaGetDeviceProperties(&prop, 0);
        g_nsm = prop.multiProcessorCount;        // 152 on GB300
        int units = n_tok >> 3;
        int hiU = (units + g_nsm - 1) / g_nsm;   // ceil
        int loU = units / g_nsm;                 // floor
        g_hi = hiU * 8;
        int lo = (loU > 0 ? loU : 1) * 8;
        // smem: ring (5*64*hi) + wt 16384 + mbar 64B
        g_smem = (NSTAGE * 64 * g_hi + 16384) * 4 + 64;
        cudaFuncSetAttribute(top2_router_kernel,
                             cudaFuncAttributeMaxDynamicSharedMemorySize, g_smem);
        build_maps(x, n_tok, g_hi, lo);
        g_last_x = x;
    } else if (g_last_x != x) {
        int units = n_tok >> 3;
        int loU = units / g_nsm;
        build_maps(x, n_tok, g_hi, (loU > 0 ? loU : 1) * 8);
        g_last_x = x;
    }

    top2_router_kernel<<<g_nsm, THREADS, g_smem>>>(g_mapHi, g_mapLo,
                                                   W, b, out, n_tok, g_hi);
}